// round 1
// baseline (speedup 1.0000x reference)
#include <cuda_runtime.h>
#include <math.h>

#define NATOMS 524288
#define DD     256
#define NB     16384
#define MSTEPS 6

// ---------------- persistent device scratch (no allocs allowed) -------------
__device__ float g_h[NB * DD];        // 16 MB
__device__ float g_c[NB * DD];        // 16 MB
__device__ float g_r[NB * DD];        // 16 MB
__device__ float g_z[NB * 4 * DD];    // 64 MB
__device__ int   g_seg[NB + 1];

// ---------------- segment offsets: binary search per molecule ---------------
__global__ void segstart_kernel(const int* __restrict__ split) {
    int j = blockIdx.x * blockDim.x + threadIdx.x;
    if (j > NB) return;
    int lo = 0, hi = NATOMS;
    while (lo < hi) {
        int mid = (lo + hi) >> 1;
        if (split[mid] < j) lo = mid + 1; else hi = mid;
    }
    g_seg[j] = lo;
}

__global__ void zero_hc_kernel() {
    int idx = blockIdx.x * blockDim.x + threadIdx.x;
    if (idx < NB * DD) { g_h[idx] = 0.f; g_c[idx] = 0.f; }
}

// ---------------- fused attention pass: one warp per molecule ---------------
// r_b = (sum_i exp(x_i . h_b) * x_i) / (sum_i exp(x_i . h_b))
__device__ __forceinline__ float dot8(float4 a0, float4 a1, float4 h0, float4 h1) {
    return a0.x*h0.x + a0.y*h0.y + a0.z*h0.z + a0.w*h0.w
         + a1.x*h1.x + a1.y*h1.y + a1.z*h1.z + a1.w*h1.w;
}

__global__ void attn_kernel(const float* __restrict__ X) {
    int gw   = (blockIdx.x * blockDim.x + threadIdx.x) >> 5;
    int lane = threadIdx.x & 31;
    if (gw >= NB) return;
    int s = g_seg[gw];
    int e = g_seg[gw + 1];

    const float* hrow = g_h + (size_t)gw * DD + lane * 8;
    float4 h0 = *(const float4*)(hrow);
    float4 h1 = *(const float4*)(hrow + 4);

    float4 A0 = make_float4(0.f, 0.f, 0.f, 0.f);
    float4 A1 = make_float4(0.f, 0.f, 0.f, 0.f);
    float sumexp = 0.f;

    int i = s;
    // unroll-2: 4 outstanding float4 loads per warp-iteration for MLP
    for (; i + 2 <= e; i += 2) {
        const float4* p0 = (const float4*)(X + (size_t)i       * DD + lane * 8);
        const float4* p1 = (const float4*)(X + (size_t)(i + 1) * DD + lane * 8);
        float4 xa0 = p0[0], xa1 = p0[1];
        float4 xb0 = p1[0], xb1 = p1[1];
        float pa = dot8(xa0, xa1, h0, h1);
        float pb = dot8(xb0, xb1, h0, h1);
        #pragma unroll
        for (int m = 16; m; m >>= 1) {
            pa += __shfl_xor_sync(0xffffffffu, pa, m);
            pb += __shfl_xor_sync(0xffffffffu, pb, m);
        }
        float wa = expf(pa);
        float wb = expf(pb);
        sumexp += wa + wb;
        A0.x += wa * xa0.x + wb * xb0.x;  A0.y += wa * xa0.y + wb * xb0.y;
        A0.z += wa * xa0.z + wb * xb0.z;  A0.w += wa * xa0.w + wb * xb0.w;
        A1.x += wa * xa1.x + wb * xb1.x;  A1.y += wa * xa1.y + wb * xb1.y;
        A1.z += wa * xa1.z + wb * xb1.z;  A1.w += wa * xa1.w + wb * xb1.w;
    }
    if (i < e) {
        const float4* p0 = (const float4*)(X + (size_t)i * DD + lane * 8);
        float4 xa0 = p0[0], xa1 = p0[1];
        float pa = dot8(xa0, xa1, h0, h1);
        #pragma unroll
        for (int m = 16; m; m >>= 1)
            pa += __shfl_xor_sync(0xffffffffu, pa, m);
        float wa = expf(pa);
        sumexp += wa;
        A0.x += wa * xa0.x; A0.y += wa * xa0.y; A0.z += wa * xa0.z; A0.w += wa * xa0.w;
        A1.x += wa * xa1.x; A1.y += wa * xa1.y; A1.z += wa * xa1.z; A1.w += wa * xa1.w;
    }

    float inv = (e > s) ? (1.0f / sumexp) : 0.f;   // empty segment -> r = 0
    float* rrow = g_r + (size_t)gw * DD + lane * 8;
    float4 r0 = make_float4(A0.x * inv, A0.y * inv, A0.z * inv, A0.w * inv);
    float4 r1 = make_float4(A1.x * inv, A1.y * inv, A1.z * inv, A1.w * inv);
    *(float4*)(rrow)     = r0;
    *(float4*)(rrow + 4) = r1;
}

// ---------------- fp32 tiled GEMM: z = [h, r] @ U + b -----------------------
// A = [NB, 512] (h cols 0..255, r cols 256..511), U = [512, 1024], Z = [NB, 1024]
__global__ void lstm_gemm_kernel(const float* __restrict__ U,
                                 const float* __restrict__ bias) {
    __shared__ float As[8][128];
    __shared__ float Bs[8][128];

    int tid = threadIdx.x;
    int block_row = blockIdx.y * 128;
    int block_col = blockIdx.x * 128;
    int tx = tid & 15, ty = tid >> 4;
    int row_base = ty * 8, col_base = tx * 8;

    int a_row = tid >> 1;            // 0..127
    int a_col = (tid & 1) * 4;       // 0 or 4
    int b_row = tid >> 5;            // 0..7
    int b_col = (tid & 31) * 4;      // 0..124

    float acc[8][8];
    #pragma unroll
    for (int i = 0; i < 8; i++)
        #pragma unroll
        for (int j = 0; j < 8; j++) acc[i][j] = 0.f;

    for (int k0 = 0; k0 < 512; k0 += 8) {
        const float* Asrc = (k0 < 256) ? g_h : g_r;
        int kk = k0 & 255;
        float4 av = *(const float4*)(Asrc + (size_t)(block_row + a_row) * DD + kk + a_col);
        float4 bv = *(const float4*)(U + (size_t)(k0 + b_row) * 1024 + block_col + b_col);
        __syncthreads();
        As[a_col + 0][a_row] = av.x;
        As[a_col + 1][a_row] = av.y;
        As[a_col + 2][a_row] = av.z;
        As[a_col + 3][a_row] = av.w;
        *(float4*)&Bs[b_row][b_col] = bv;
        __syncthreads();
        #pragma unroll
        for (int k = 0; k < 8; k++) {
            float4 a0 = *(const float4*)&As[k][row_base];
            float4 a1 = *(const float4*)&As[k][row_base + 4];
            float4 b0 = *(const float4*)&Bs[k][col_base];
            float4 b1 = *(const float4*)&Bs[k][col_base + 4];
            float ar[8] = {a0.x, a0.y, a0.z, a0.w, a1.x, a1.y, a1.z, a1.w};
            float br[8] = {b0.x, b0.y, b0.z, b0.w, b1.x, b1.y, b1.z, b1.w};
            #pragma unroll
            for (int ii = 0; ii < 8; ii++)
                #pragma unroll
                for (int jj = 0; jj < 8; jj++)
                    acc[ii][jj] += ar[ii] * br[jj];
        }
    }

    float bv[8];
    #pragma unroll
    for (int j = 0; j < 8; j++) bv[j] = bias[block_col + col_base + j];
    #pragma unroll
    for (int ii = 0; ii < 8; ii++) {
        float* zp = g_z + (size_t)(block_row + row_base + ii) * 1024 + block_col + col_base;
        float4 v0 = make_float4(acc[ii][0] + bv[0], acc[ii][1] + bv[1],
                                acc[ii][2] + bv[2], acc[ii][3] + bv[3]);
        float4 v1 = make_float4(acc[ii][4] + bv[4], acc[ii][5] + bv[5],
                                acc[ii][6] + bv[6], acc[ii][7] + bv[7]);
        *(float4*)(zp)     = v0;
        *(float4*)(zp + 4) = v1;
    }
}

// ---------------- LSTM gates ------------------------------------------------
__global__ void gates_kernel() {
    int idx = blockIdx.x * blockDim.x + threadIdx.x;
    if (idx >= NB * DD) return;
    int row = idx >> 8, d = idx & 255;
    const float* zr = g_z + (size_t)row * 1024;
    float zi = zr[d], zf = zr[256 + d], zo = zr[512 + d], zg = zr[768 + d];
    float ig = 1.f / (1.f + expf(-zi));
    float fg = 1.f / (1.f + expf(-zf));
    float og = 1.f / (1.f + expf(-zo));
    float gg = tanhf(zg);
    float c = fg * g_c[idx] + ig * gg;
    g_c[idx] = c;
    g_h[idx] = og * tanhf(c);
}

// ---------------- final output: q_star = concat(h, r) -----------------------
__global__ void concat_kernel(float* __restrict__ out) {
    int idx = blockIdx.x * blockDim.x + threadIdx.x;
    if (idx >= NB * DD) return;
    int row = idx >> 8, d = idx & 255;
    out[(size_t)row * 2 * DD + d]      = g_h[idx];
    out[(size_t)row * 2 * DD + DD + d] = g_r[idx];
}

// -----------------------------------------------------------------------------
extern "C" void kernel_launch(void* const* d_in, const int* in_sizes, int n_in,
                              void* d_out, int out_size) {
    (void)in_sizes; (void)n_in; (void)out_size;
    const float* X     = (const float*)d_in[0];   // [NATOMS, 256]
    const int*   split = (const int*)  d_in[1];   // [NATOMS]
    const float* U     = (const float*)d_in[2];   // [512, 1024]
    const float* bias  = (const float*)d_in[3];   // [1024]
    float* out = (float*)d_out;                   // [NB, 512]

    segstart_kernel<<<(NB + 1 + 255) / 256, 256>>>(split);
    zero_hc_kernel<<<(NB * DD + 255) / 256, 256>>>();

    dim3 gemm_grid(1024 / 128, NB / 128);   // (8, 128)
    int attn_blocks = NB / 8;               // 8 warps (molecules) per 256-thread block

    for (int step = 0; step < MSTEPS; step++) {
        attn_kernel<<<attn_blocks, 256>>>(X);
        if (step < MSTEPS - 1) {            // last step: only q_star needed
            lstm_gemm_kernel<<<gemm_grid, 256>>>(U, bias);
            gates_kernel<<<(NB * DD) / 256, 256>>>();
        }
    }
    concat_kernel<<<(NB * DD) / 256, 256>>>(out);
}

// round 3
// speedup vs baseline: 2.0417x; 2.0417x over previous
#include <cuda_runtime.h>
#include <cuda_bf16.h>
#include <math.h>
#include <stdint.h>

#define NATOMS 524288
#define DD     256
#define NB     16384
#define MSTEPS 6

// ---------------- persistent device scratch (no allocs allowed) -------------
__device__ float g_h[NB * DD];                 // 16 MB
__device__ float g_c[NB * DD];                 // 16 MB
__device__ float g_r[NB * DD];                 // 16 MB
__device__ float g_z[NB * 4 * DD];             // 64 MB
__device__ __nv_bfloat16 g_Ahi[NB * 512];      // A = [h,r] hi part
__device__ __nv_bfloat16 g_Alo[NB * 512];      // A lo part
__device__ __nv_bfloat16 g_UThi[1024 * 512];   // U^T hi: [n][k]
__device__ __nv_bfloat16 g_UTlo[1024 * 512];   // U^T lo
__device__ int   g_seg[NB + 1];

// ---------------- helpers -----------------------------------------------------
__device__ __forceinline__ uint32_t smem_u32(const void* p) {
    uint32_t a;
    asm("{ .reg .u64 t; cvta.to.shared.u64 t, %1; cvt.u32.u64 %0, t; }" : "=r"(a) : "l"(p));
    return a;
}

__device__ __forceinline__ void cp_async16(uint32_t dst, const void* src) {
    asm volatile("cp.async.cg.shared.global [%0], [%1], 16;" :: "r"(dst), "l"(src) : "memory");
}

__device__ __forceinline__ void ldm_x4(uint32_t* r, uint32_t addr) {
    asm volatile("ldmatrix.sync.aligned.m8n8.x4.shared.b16 {%0,%1,%2,%3}, [%4];"
                 : "=r"(r[0]), "=r"(r[1]), "=r"(r[2]), "=r"(r[3]) : "r"(addr));
}

__device__ __forceinline__ void mma16816(float* d, const uint32_t* a, const uint32_t* b) {
    asm volatile(
        "mma.sync.aligned.m16n8k16.row.col.f32.bf16.bf16.f32 "
        "{%0,%1,%2,%3}, {%4,%5,%6,%7}, {%8,%9}, {%0,%1,%2,%3};"
        : "+f"(d[0]), "+f"(d[1]), "+f"(d[2]), "+f"(d[3])
        : "r"(a[0]), "r"(a[1]), "r"(a[2]), "r"(a[3]), "r"(b[0]), "r"(b[1]));
}

// ---------------- segment offsets --------------------------------------------
__global__ void segstart_kernel(const int* __restrict__ split) {
    int j = blockIdx.x * blockDim.x + threadIdx.x;
    if (j > NB) return;
    int lo = 0, hi = NATOMS;
    while (lo < hi) { int mid = (lo + hi) >> 1; if (split[mid] < j) lo = mid + 1; else hi = mid; }
    g_seg[j] = lo;
}

__global__ void zero_hc_kernel() {
    int idx = blockIdx.x * blockDim.x + threadIdx.x;
    if (idx >= NB * DD) return;
    g_h[idx] = 0.f; g_c[idx] = 0.f;
    int row = idx >> 8, d = idx & 255;
    g_Ahi[(size_t)row * 512 + d] = __float2bfloat16(0.f);
    g_Alo[(size_t)row * 512 + d] = __float2bfloat16(0.f);
}

// ---------------- prep U: transpose + bf16 split, once ------------------------
__global__ void prep_U_kernel(const float* __restrict__ U) {
    __shared__ float tile[32][33];
    int bx = blockIdx.x;  // n-tile: 0..31
    int by = blockIdx.y;  // k-tile: 0..15
    int tx = threadIdx.x & 31, ty = threadIdx.x >> 5;
    #pragma unroll
    for (int j = 0; j < 4; j++) {
        int k = by * 32 + ty + j * 8;
        int n = bx * 32 + tx;
        tile[ty + j * 8][tx] = U[(size_t)k * 1024 + n];
    }
    __syncthreads();
    #pragma unroll
    for (int j = 0; j < 4; j++) {
        int n = bx * 32 + ty + j * 8;
        int k = by * 32 + tx;
        float v = tile[tx][ty + j * 8];
        __nv_bfloat16 hi = __float2bfloat16(v);
        float lo = v - __bfloat162float(hi);
        g_UThi[(size_t)n * 512 + k] = hi;
        g_UTlo[(size_t)n * 512 + k] = __float2bfloat16(lo);
    }
}

// ---------------- fused attention pass: one warp per molecule ----------------
__device__ __forceinline__ float dot8(float4 a0, float4 a1, float4 h0, float4 h1) {
    return a0.x*h0.x + a0.y*h0.y + a0.z*h0.z + a0.w*h0.w
         + a1.x*h1.x + a1.y*h1.y + a1.z*h1.z + a1.w*h1.w;
}

__global__ void attn_kernel(const float* __restrict__ X) {
    int gw   = (blockIdx.x * blockDim.x + threadIdx.x) >> 5;
    int lane = threadIdx.x & 31;
    if (gw >= NB) return;
    int s = g_seg[gw];
    int e = g_seg[gw + 1];

    const float* hrow = g_h + (size_t)gw * DD + lane * 8;
    float4 h0 = *(const float4*)(hrow);
    float4 h1 = *(const float4*)(hrow + 4);

    float4 A0 = make_float4(0.f, 0.f, 0.f, 0.f);
    float4 A1 = make_float4(0.f, 0.f, 0.f, 0.f);
    float sumexp = 0.f;

    int i = s;
    for (; i + 2 <= e; i += 2) {
        const float4* p0 = (const float4*)(X + (size_t)i       * DD + lane * 8);
        const float4* p1 = (const float4*)(X + (size_t)(i + 1) * DD + lane * 8);
        float4 xa0 = p0[0], xa1 = p0[1];
        float4 xb0 = p1[0], xb1 = p1[1];
        float pa = dot8(xa0, xa1, h0, h1);
        float pb = dot8(xb0, xb1, h0, h1);
        #pragma unroll
        for (int m = 16; m; m >>= 1) {
            pa += __shfl_xor_sync(0xffffffffu, pa, m);
            pb += __shfl_xor_sync(0xffffffffu, pb, m);
        }
        float wa = expf(pa);
        float wb = expf(pb);
        sumexp += wa + wb;
        A0.x += wa * xa0.x + wb * xb0.x;  A0.y += wa * xa0.y + wb * xb0.y;
        A0.z += wa * xa0.z + wb * xb0.z;  A0.w += wa * xa0.w + wb * xb0.w;
        A1.x += wa * xa1.x + wb * xb1.x;  A1.y += wa * xa1.y + wb * xb1.y;
        A1.z += wa * xa1.z + wb * xb1.z;  A1.w += wa * xa1.w + wb * xb1.w;
    }
    if (i < e) {
        const float4* p0 = (const float4*)(X + (size_t)i * DD + lane * 8);
        float4 xa0 = p0[0], xa1 = p0[1];
        float pa = dot8(xa0, xa1, h0, h1);
        #pragma unroll
        for (int m = 16; m; m >>= 1) pa += __shfl_xor_sync(0xffffffffu, pa, m);
        float wa = expf(pa);
        sumexp += wa;
        A0.x += wa * xa0.x; A0.y += wa * xa0.y; A0.z += wa * xa0.z; A0.w += wa * xa0.w;
        A1.x += wa * xa1.x; A1.y += wa * xa1.y; A1.z += wa * xa1.z; A1.w += wa * xa1.w;
    }

    float inv = (e > s) ? (1.0f / sumexp) : 0.f;
    float r[8] = {A0.x*inv, A0.y*inv, A0.z*inv, A0.w*inv,
                  A1.x*inv, A1.y*inv, A1.z*inv, A1.w*inv};
    float* rrow = g_r + (size_t)gw * DD + lane * 8;
    *(float4*)(rrow)     = make_float4(r[0], r[1], r[2], r[3]);
    *(float4*)(rrow + 4) = make_float4(r[4], r[5], r[6], r[7]);

    __nv_bfloat16 hi8[8], lo8[8];
    #pragma unroll
    for (int t = 0; t < 8; t++) {
        hi8[t] = __float2bfloat16(r[t]);
        lo8[t] = __float2bfloat16(r[t] - __bfloat162float(hi8[t]));
    }
    *(uint4*)(g_Ahi + (size_t)gw * 512 + 256 + lane * 8) = *(uint4*)hi8;
    *(uint4*)(g_Alo + (size_t)gw * 512 + 256 + lane * 8) = *(uint4*)lo8;
}

// ---------------- HMMA GEMM: Z = [h,r] @ U + bias -----------------------------
// CTA 128x128, BK=32, double-buffered cp.async. 8 warps, warp tile 32x64.
// 3-term bf16 split: Ahi*Bhi + Ahi*Blo + Alo*Bhi, fp32 accum.
#define BK       32
#define KTILES   16              // 512 / 32
#define LDS_PAD  40              // halves per row (32 data + 8 pad); 80 bytes
#define SA_HI    0
#define SA_LO    10240
#define SB_HI    20480
#define SB_LO    30720
#define STAGE_B  40960
#define SMEM_TOT (2 * STAGE_B)

__device__ __forceinline__ void load_stage(uint32_t sdst, int kbase,
                                           int block_row, int block_col, int tid) {
    #pragma unroll
    for (int halfp = 0; halfp < 2; halfp++) {
        int c   = tid + halfp * 256;     // 0..511
        int row = c >> 2;                // 0..127
        int seg = c & 3;                 // 16B segment
        uint32_t doff = (uint32_t)(row * 80 + seg * 16);
        size_t aoff = (size_t)(block_row + row) * 512 + kbase + seg * 8;
        size_t boff = (size_t)(block_col + row) * 512 + kbase + seg * 8;
        cp_async16(sdst + SA_HI + doff, g_Ahi  + aoff);
        cp_async16(sdst + SA_LO + doff, g_Alo  + aoff);
        cp_async16(sdst + SB_HI + doff, g_UThi + boff);
        cp_async16(sdst + SB_LO + doff, g_UTlo + boff);
    }
}

__global__ void __launch_bounds__(256)
lstm_gemm_mma_kernel(const float* __restrict__ bias) {
    extern __shared__ char smem[];
    uint32_t smem_base = smem_u32(smem);
    int tid  = threadIdx.x;
    int wid  = tid >> 5;
    int lane = tid & 31;
    int warp_m = wid & 3;    // 4 warps over M
    int warp_n = wid >> 2;   // 2 warps over N
    int block_row = blockIdx.y * 128;
    int block_col = blockIdx.x * 128;

    float acc[2][8][4];
    #pragma unroll
    for (int i = 0; i < 2; i++)
        #pragma unroll
        for (int j = 0; j < 8; j++)
            #pragma unroll
            for (int t = 0; t < 4; t++) acc[i][j][t] = 0.f;

    // ldmatrix source addresses (per-buffer base added in loop)
    int a_row = warp_m * 32 + (lane & 15);
    int a_colsel = (lane >> 4) * 8;
    int b_row = warp_n * 64 + ((lane >> 4) << 3) + (lane & 7);
    int b_colsel = ((lane >> 3) & 1) * 8;

    load_stage(smem_base, 0, block_row, block_col, tid);
    asm volatile("cp.async.commit_group;" ::: "memory");

    for (int kt = 0; kt < KTILES; kt++) {
        if (kt + 1 < KTILES) {
            load_stage(smem_base + ((kt + 1) & 1) * STAGE_B, (kt + 1) * BK,
                       block_row, block_col, tid);
            asm volatile("cp.async.commit_group;" ::: "memory");
            asm volatile("cp.async.wait_group 1;" ::: "memory");
        } else {
            asm volatile("cp.async.wait_group 0;" ::: "memory");
        }
        __syncthreads();

        uint32_t sbase = smem_base + (kt & 1) * STAGE_B;
        #pragma unroll
        for (int ksub = 0; ksub < 2; ksub++) {
            uint32_t a_hi[2][4], a_lo[2][4];
            #pragma unroll
            for (int mt = 0; mt < 2; mt++) {
                uint32_t off = (uint32_t)((a_row + mt * 16) * 80
                               + (ksub * 16 + a_colsel) * 2);
                ldm_x4(a_hi[mt], sbase + SA_HI + off);
                ldm_x4(a_lo[mt], sbase + SA_LO + off);
            }
            uint32_t b_hi[4][4], b_lo[4][4];
            #pragma unroll
            for (int nt2 = 0; nt2 < 4; nt2++) {
                uint32_t off = (uint32_t)((b_row + nt2 * 16) * 80
                               + (ksub * 16 + b_colsel) * 2);
                ldm_x4(b_hi[nt2], sbase + SB_HI + off);
                ldm_x4(b_lo[nt2], sbase + SB_LO + off);
            }
            #pragma unroll
            for (int mt = 0; mt < 2; mt++) {
                #pragma unroll
                for (int nt = 0; nt < 8; nt++) {
                    const uint32_t* bh = &b_hi[nt >> 1][(nt & 1) * 2];
                    const uint32_t* bl = &b_lo[nt >> 1][(nt & 1) * 2];
                    mma16816(acc[mt][nt], a_hi[mt], bh);
                    mma16816(acc[mt][nt], a_hi[mt], bl);
                    mma16816(acc[mt][nt], a_lo[mt], bh);
                }
            }
        }
        __syncthreads();
    }

    // epilogue: bias add + direct store (float2)
    #pragma unroll
    for (int nt = 0; nt < 8; nt++) {
        int c = block_col + warp_n * 64 + nt * 8 + (lane & 3) * 2;
        float bv0 = bias[c], bv1 = bias[c + 1];
        #pragma unroll
        for (int mt = 0; mt < 2; mt++) {
            int r0 = block_row + warp_m * 32 + mt * 16 + (lane >> 2);
            float2 v0 = make_float2(acc[mt][nt][0] + bv0, acc[mt][nt][1] + bv1);
            float2 v1 = make_float2(acc[mt][nt][2] + bv0, acc[mt][nt][3] + bv1);
            *(float2*)(g_z + (size_t)r0 * 1024 + c)       = v0;
            *(float2*)(g_z + (size_t)(r0 + 8) * 1024 + c) = v1;
        }
    }
}

// ---------------- LSTM gates (writes h fp32 + bf16 hi/lo into A cols 0..255) --
__global__ void gates_kernel() {
    int idx = blockIdx.x * blockDim.x + threadIdx.x;
    if (idx >= NB * DD) return;
    int row = idx >> 8, d = idx & 255;
    const float* zr = g_z + (size_t)row * 1024;
    float zi = zr[d], zf = zr[256 + d], zo = zr[512 + d], zg = zr[768 + d];
    float ig = 1.f / (1.f + expf(-zi));
    float fg = 1.f / (1.f + expf(-zf));
    float og = 1.f / (1.f + expf(-zo));
    float gg = tanhf(zg);
    float c = fg * g_c[idx] + ig * gg;
    g_c[idx] = c;
    float h = og * tanhf(c);
    g_h[idx] = h;
    __nv_bfloat16 hi = __float2bfloat16(h);
    g_Ahi[(size_t)row * 512 + d] = hi;
    g_Alo[(size_t)row * 512 + d] = __float2bfloat16(h - __bfloat162float(hi));
}

// ---------------- final output: q_star = concat(h, r) -------------------------
__global__ void concat_kernel(float* __restrict__ out) {
    int idx = blockIdx.x * blockDim.x + threadIdx.x;
    if (idx >= NB * DD) return;
    int row = idx >> 8, d = idx & 255;
    out[(size_t)row * 2 * DD + d]      = g_h[idx];
    out[(size_t)row * 2 * DD + DD + d] = g_r[idx];
}

// ------------------------------------------------------------------------------
extern "C" void kernel_launch(void* const* d_in, const int* in_sizes, int n_in,
                              void* d_out, int out_size) {
    (void)in_sizes; (void)n_in; (void)out_size;
    const float* X     = (const float*)d_in[0];   // [NATOMS, 256]
    const int*   split = (const int*)  d_in[1];   // [NATOMS]
    const float* U     = (const float*)d_in[2];   // [512, 1024]
    const float* bias  = (const float*)d_in[3];   // [1024]
    float* out = (float*)d_out;                   // [NB, 512]

    cudaFuncSetAttribute(lstm_gemm_mma_kernel,
                         cudaFuncAttributeMaxDynamicSharedMemorySize, SMEM_TOT);

    segstart_kernel<<<(NB + 1 + 255) / 256, 256>>>(split);
    zero_hc_kernel<<<(NB * DD + 255) / 256, 256>>>();
    {
        dim3 tg(32, 16);
        prep_U_kernel<<<tg, 256>>>(U);
    }

    dim3 gemm_grid(8, 128);                 // 1024 CTAs, 128x128 tiles
    int attn_blocks = NB / 8;               // 8 warps per 256-thread block

    for (int step = 0; step < MSTEPS; step++) {
        attn_kernel<<<attn_blocks, 256>>>(X);
        if (step < MSTEPS - 1) {            // last step: only q_star needed
            lstm_gemm_mma_kernel<<<gemm_grid, 256, SMEM_TOT>>>(bias);
            gates_kernel<<<(NB * DD) / 256, 256>>>();
        }
    }
    concat_kernel<<<(NB * DD) / 256, 256>>>(out);
}